// round 3
// baseline (speedup 1.0000x reference)
#include <cuda_runtime.h>
#include <math_constants.h>

// Problem constants
constexpr int B = 32, S = 4, K = 11, C = 9, H = 128, W = 128;
constexpr int HW = H * W;          // 16384
constexpr int BK = B * K;          // 352 blocks
constexpr int BS = B * S;          // 128

// Zero-init the output (poisoned by harness; we accumulate with atomics).
__global__ __launch_bounds__(256) void kp_zero_kernel(float* __restrict__ out) {
    out[threadIdx.x] = 0.0f;       // exactly 2*BS = 256 elements
}

// One block per (b,k): streams the heatmap plane ONCE against all S=4
// pred planes, keeping 4 independent (sumsq, max, argmax) accumulators.
// Epilogue: warps 0..3 each finish one stack s (gathers + atomics).
__global__ __launch_bounds__(256) void kp_fused_kernel(
    const float* __restrict__ hm_preds,   // [B,S,K,H,W]
    const float* __restrict__ lb_preds,   // [B,S,C,H,W]
    const float* __restrict__ heatmaps,   // [B,K,H,W]
    const float* __restrict__ labels,     // [B,K,11]
    float* __restrict__ out)              // [2*B*S]: [hm | lb]
{
    const int blk = blockIdx.x;           // b*K + k
    const int k = blk % K;
    const int b = blk / K;

    const float4* __restrict__ g =
        reinterpret_cast<const float4*>(heatmaps + ((size_t)b * K + k) * HW);
    // stack s plane: hm_preds + ((b*S+s)*K + k)*HW ; stride K*HW between s
    const float4* __restrict__ p0 =
        reinterpret_cast<const float4*>(hm_preds + ((size_t)b * S * K + k) * HW);
    constexpr size_t SSTRIDE = (size_t)K * HW / 4;   // in float4s

    const int tid = threadIdx.x;

    float sq[S];
    float mx[S];
    int   mi[S];
    #pragma unroll
    for (int s = 0; s < S; s++) { sq[s] = 0.0f; mx[s] = -CUDART_INF_F; mi[s] = 0; }

    // HW/4 = 4096 float4s, 256 threads -> 16 iterations/thread
    #pragma unroll 2
    for (int i = tid; i < HW / 4; i += 256) {
        const float4 gv = __ldcs(&g[i]);
        const int base = i * 4;
        #pragma unroll
        for (int s = 0; s < S; s++) {
            const float4 pv = __ldcs(&p0[(size_t)s * SSTRIDE + i]);
            float d0 = pv.x - gv.x, d1 = pv.y - gv.y;
            float d2 = pv.z - gv.z, d3 = pv.w - gv.w;
            sq[s] += d0 * d0 + d1 * d1 + d2 * d2 + d3 * d3;
            // strict > keeps the lowest index within this thread (ascending)
            if (pv.x > mx[s]) { mx[s] = pv.x; mi[s] = base;     }
            if (pv.y > mx[s]) { mx[s] = pv.y; mi[s] = base + 1; }
            if (pv.z > mx[s]) { mx[s] = pv.z; mi[s] = base + 2; }
            if (pv.w > mx[s]) { mx[s] = pv.w; mi[s] = base + 3; }
        }
    }

    // Warp reduction per stack (sum + argmax, first-index tiebreak)
    #pragma unroll
    for (int s = 0; s < S; s++) {
        #pragma unroll
        for (int off = 16; off > 0; off >>= 1) {
            sq[s] += __shfl_down_sync(0xFFFFFFFFu, sq[s], off);
            float omx = __shfl_down_sync(0xFFFFFFFFu, mx[s], off);
            int   omi = __shfl_down_sync(0xFFFFFFFFu, mi[s], off);
            if (omx > mx[s] || (omx == mx[s] && omi < mi[s])) {
                mx[s] = omx; mi[s] = omi;
            }
        }
    }

    __shared__ float s_sq[S][8];
    __shared__ float s_mx[S][8];
    __shared__ int   s_mi[S][8];
    const int wid = tid >> 5, lane = tid & 31;
    if (lane == 0) {
        #pragma unroll
        for (int s = 0; s < S; s++) {
            s_sq[s][wid] = sq[s];
            s_mx[s][wid] = mx[s];
            s_mi[s][wid] = mi[s];
        }
    }
    __syncthreads();

    // Warps 0..3 each finish one stack
    if (wid < S) {
        const int s = wid;
        float fsq = (lane < 8) ? s_sq[s][lane] : 0.0f;
        float fmx = (lane < 8) ? s_mx[s][lane] : -CUDART_INF_F;
        int   fmi = (lane < 8) ? s_mi[s][lane] : 0x7FFFFFFF;
        #pragma unroll
        for (int off = 4; off > 0; off >>= 1) {
            fsq += __shfl_down_sync(0xFFFFFFFFu, fsq, off);
            float omx = __shfl_down_sync(0xFFFFFFFFu, fmx, off);
            int   omi = __shfl_down_sync(0xFFFFFFFFu, fmi, off);
            if (omx > fmx || (omx == fmx && omi < fmi)) { fmx = omx; fmi = omi; }
        }
        // broadcast final to whole warp
        fsq = __shfl_sync(0xFFFFFFFFu, fsq, 0);
        fmx = __shfl_sync(0xFFFFFFFFu, fmx, 0);
        fmi = __shfl_sync(0xFFFFFFFFu, fmi, 0);

        const int bs = b * S + s;
        const float* __restrict__ lab = labels + ((size_t)b * K + k) * 11;

        // lanes 0..8: one class-channel gather each at the argmax position
        float part = 0.0f;
        if (lane < C) {
            const float v = __ldg(&lb_preds[((size_t)bs * C + lane) * HW + fmi]);
            const float d = v - __ldg(&lab[lane]);
            part = d * d;
        }
        #pragma unroll
        for (int off = 8; off > 0; off >>= 1)
            part += __shfl_down_sync(0xFFFFFFFFu, part, off);

        if (lane == 0) {
            const float gx = __ldg(&lab[9]);
            const float gy = __ldg(&lab[10]);
            const bool valid = (gx >= 0.0f) && (gy >= 0.0f) &&
                               (gx < (float)H) && (gy < (float)W);
            const int x = fmi / W;  // m == H == W == 128: pos == idx
            const int y = fmi % W;
            const float dx = gx - (float)x;
            const float dy = gy - (float)y;
            const float cf = 1.0f - fmx;
            const float lb = valid ? (part + dx * dx + dy * dy + cf * cf) : 0.0f;

            atomicAdd(&out[bs],      fsq);  // hm_loss [B,S]
            atomicAdd(&out[BS + bs], lb);   // lb_loss [B,S]
        }
    }
}

extern "C" void kernel_launch(void* const* d_in, const int* in_sizes, int n_in,
                              void* d_out, int out_size) {
    const float* hm_preds = (const float*)d_in[0];  // [B,S,K,H,W]
    const float* lb_preds = (const float*)d_in[1];  // [B,S,C,H,W]
    const float* heatmaps = (const float*)d_in[2];  // [B,K,H,W]
    const float* labels   = (const float*)d_in[3];  // [B,K,11]
    float* out = (float*)d_out;

    kp_zero_kernel<<<1, 2 * BS>>>(out);
    kp_fused_kernel<<<BK, 256>>>(hm_preds, lb_preds, heatmaps, labels, out);
}